// round 1
// baseline (speedup 1.0000x reference)
#include <cuda_runtime.h>
#include <math.h>
#include <stdint.h>

#define DIMC 256
#define HEADS 8
#define HEAD_DIM 32
#define WSZ 8
#define NTOK 64            // tokens per window (8x8)
#define BATCH 32
#define HH 64
#define WWID 64
#define LTOK (HH*WWID)     // 4096
#define M_ROWS (BATCH*LTOK)  // 131072
#define SHIFT_ 4

// ---------------- scratch (static device globals; no allocation) ----------------
static __device__ float g_xw[(size_t)M_ROWS * DIMC];          // 134 MB windowed x
static __device__ float g_qkv[(size_t)M_ROWS * 3 * DIMC];     // 402 MB
static __device__ float g_attnout[(size_t)M_ROWS * DIMC];     // 134 MB
static __device__ float g_tmp[(size_t)M_ROWS * DIMC];         // 134 MB (proj out, then fc2 out)
static __device__ float g_xr[(size_t)M_ROWS * DIMC];          // 134 MB
static __device__ float g_hdn[(size_t)M_ROWS * 4 * DIMC];     // 537 MB
static __device__ float g_cpb[225 * HEADS];
static __device__ float g_bias16[HEADS * NTOK * NTOK];
static __device__ float g_qkvb[3 * DIMC];

// ---------------- tiny setup kernels ----------------
__global__ void fill_qkvb_kernel(const float* __restrict__ q_bias,
                                 const float* __restrict__ v_bias) {
    int t = threadIdx.x;  // 768
    float v;
    if (t < 256)      v = q_bias[t];
    else if (t < 512) v = 0.f;
    else              v = v_bias[t - 512];
    g_qkvb[t] = v;
}

// CPB MLP: coords(225,2) -> relu(512) -> (heads)
__global__ void cpb_kernel(const float* __restrict__ w1, const float* __restrict__ b1,
                           const float* __restrict__ w2) {
    int i = threadIdx.x;
    if (i >= 225) return;
    float a  = (float)(i / 15) - 7.f;
    float bb = (float)(i % 15) - 7.f;
    float f0 = a  * (8.f / 7.f);
    float f1 = bb * (8.f / 7.f);
    f0 = copysignf(log2f(fabsf(f0) + 1.f) * (1.f / 3.f), f0);
    f1 = copysignf(log2f(fabsf(f1) + 1.f) * (1.f / 3.f), f1);
    float acc[HEADS];
#pragma unroll
    for (int h = 0; h < HEADS; h++) acc[h] = 0.f;
    for (int u = 0; u < 512; u++) {
        float hu = fmaf(w1[2 * u], f0, fmaf(w1[2 * u + 1], f1, b1[u]));
        hu = fmaxf(hu, 0.f);
#pragma unroll
        for (int h = 0; h < HEADS; h++) acc[h] = fmaf(hu, w2[h * 512 + u], acc[h]);
    }
#pragma unroll
    for (int h = 0; h < HEADS; h++) g_cpb[i * HEADS + h] = acc[h];
}

// Expand to 16*sigmoid(rpb) table: (heads, 64, 64)
__global__ void bias16_kernel() {
    int gid = blockIdx.x * blockDim.x + threadIdx.x;  // 8*4096
    if (gid >= HEADS * NTOK * NTOK) return;
    int h = gid >> 12;
    int ij = gid & 4095;
    int i = ij >> 6, j = ij & 63;
    int dr = (i >> 3) - (j >> 3);
    int dc = (i & 7) - (j & 7);
    int idx = (dr + 7) * 15 + (dc + 7);
    float x = g_cpb[idx * HEADS + h];
    g_bias16[gid] = 16.f / (1.f + expf(-x));
}

// ---------------- shift + window partition gather ----------------
__global__ void gather_win_kernel(const float* __restrict__ x) {
    int t = blockIdx.x * blockDim.x + threadIdx.x;  // over M_ROWS*64 float4
    int m = t >> 6, c4 = t & 63;
    int win = m >> 6, n = m & 63;
    int b = win >> 6, wr = (win >> 3) & 7, wc = win & 7;
    int ir = n >> 3, ic = n & 7;
    int r = (wr * 8 + ir + SHIFT_) & 63;
    int c = (wc * 8 + ic + SHIFT_) & 63;
    const float4* src = (const float4*)(x + ((size_t)b * LTOK + r * 64 + c) * DIMC);
    ((float4*)(g_xw + (size_t)m * DIMC))[c4] = src[c4];
}

// ---------------- generic SIMT fp32 GEMM: C[M,N] = A[M,K] @ W[N,K]^T + bias ----------------
#define BM 128
#define BN 64
#define BK 16
__global__ __launch_bounds__(256) void gemm_kernel(
    const float* __restrict__ A, const float* __restrict__ W,
    const float* __restrict__ bias, float* __restrict__ C,
    int N, int K, int gelu) {
    __shared__ float As[BK][BM + 4];
    __shared__ float Ws[BK][BN + 4];
    int tid = threadIdx.x;
    int brow = blockIdx.y * BM;
    int bcol = blockIdx.x * BN;
    int ty = tid >> 4, tx = tid & 15;
    float acc[8][4];
#pragma unroll
    for (int i = 0; i < 8; i++)
#pragma unroll
        for (int j = 0; j < 4; j++) acc[i][j] = 0.f;

    for (int k0 = 0; k0 < K; k0 += BK) {
#pragma unroll
        for (int f = tid; f < (BM * BK / 4); f += 256) {
            int row = f >> 2, kc = (f & 3) * 4;
            float4 v = *(const float4*)(A + (size_t)(brow + row) * K + k0 + kc);
            As[kc + 0][row] = v.x; As[kc + 1][row] = v.y;
            As[kc + 2][row] = v.z; As[kc + 3][row] = v.w;
        }
        {
            int f = tid;  // BN*BK/4 == 256
            int row = f >> 2, kc = (f & 3) * 4;
            float4 v = *(const float4*)(W + (size_t)(bcol + row) * K + k0 + kc);
            Ws[kc + 0][row] = v.x; Ws[kc + 1][row] = v.y;
            Ws[kc + 2][row] = v.z; Ws[kc + 3][row] = v.w;
        }
        __syncthreads();
#pragma unroll
        for (int kk = 0; kk < BK; kk++) {
            float4 b4 = *(const float4*)&Ws[kk][tx * 4];
            float4 a4 = *(const float4*)&As[kk][ty * 8];
            float4 a5 = *(const float4*)&As[kk][ty * 8 + 4];
            float av[8] = {a4.x, a4.y, a4.z, a4.w, a5.x, a5.y, a5.z, a5.w};
            float bv[4] = {b4.x, b4.y, b4.z, b4.w};
#pragma unroll
            for (int i = 0; i < 8; i++)
#pragma unroll
                for (int j = 0; j < 4; j++) acc[i][j] = fmaf(av[i], bv[j], acc[i][j]);
        }
        __syncthreads();
    }
    float4 bfv = *(const float4*)(bias + bcol + tx * 4);
    float bv[4] = {bfv.x, bfv.y, bfv.z, bfv.w};
#pragma unroll
    for (int i = 0; i < 8; i++) {
        int row = brow + ty * 8 + i;
        float4 o;
        float vv[4];
#pragma unroll
        for (int j = 0; j < 4; j++) {
            float cvv = acc[i][j] + bv[j];
            if (gelu) cvv = 0.5f * cvv * (1.f + erff(cvv * 0.70710678118654752f));
            vv[j] = cvv;
        }
        o.x = vv[0]; o.y = vv[1]; o.z = vv[2]; o.w = vv[3];
        *(float4*)(C + (size_t)row * N + bcol + tx * 4) = o;
    }
}

// ---------------- fused window attention: one block per (window, head) ----------------
__global__ __launch_bounds__(256) void attn_kernel(const float* __restrict__ logit_scale) {
    __shared__ float qs[NTOK][33];
    __shared__ float ks[NTOK][33];
    __shared__ float vs[NTOK][33];
    __shared__ float Ss[NTOK][65];
    __shared__ int lab[NTOK];

    int blk = blockIdx.x;
    int win = blk >> 3, h = blk & 7;
    int t = threadIdx.x;

    size_t base = (size_t)win * NTOK * 768;
#pragma unroll
    for (int f = t; f < 512; f += 256) {
        int n = f >> 3, d4 = (f & 7) * 4;
        const float* rowp = g_qkv + base + (size_t)n * 768 + h * 32 + d4;
        float4 q4 = *(const float4*)(rowp);
        float4 k4 = *(const float4*)(rowp + 256);
        float4 v4 = *(const float4*)(rowp + 512);
        qs[n][d4] = q4.x; qs[n][d4 + 1] = q4.y; qs[n][d4 + 2] = q4.z; qs[n][d4 + 3] = q4.w;
        ks[n][d4] = k4.x; ks[n][d4 + 1] = k4.y; ks[n][d4 + 2] = k4.z; ks[n][d4 + 3] = k4.w;
        vs[n][d4] = v4.x; vs[n][d4 + 1] = v4.y; vs[n][d4 + 2] = v4.z; vs[n][d4 + 3] = v4.w;
    }
    if (t < NTOK) {
        int wr = (win >> 3) & 7, wc = win & 7;
        int rs = wr * 8 + (t >> 3), cs = wc * 8 + (t & 7);
        int lr = rs < 56 ? 0 : (rs < 60 ? 1 : 2);
        int lc = cs < 56 ? 0 : (cs < 60 ? 1 : 2);
        lab[t] = lr * 3 + lc;
    }
    __syncthreads();

    // cosine-normalize q,k rows: 4 threads per row, 8 elems each
    {
        int row = t >> 2, j0 = (t & 3) * 8;
        float sq = 0.f, sk = 0.f;
#pragma unroll
        for (int j = 0; j < 8; j++) {
            float a = qs[row][j0 + j]; sq = fmaf(a, a, sq);
            float b = ks[row][j0 + j]; sk = fmaf(b, b, sk);
        }
        sq += __shfl_xor_sync(0xffffffffu, sq, 1);
        sq += __shfl_xor_sync(0xffffffffu, sq, 2);
        sk += __shfl_xor_sync(0xffffffffu, sk, 1);
        sk += __shfl_xor_sync(0xffffffffu, sk, 2);
        float iq = 1.f / fmaxf(sqrtf(sq), 1e-12f);
        float ik = 1.f / fmaxf(sqrtf(sk), 1e-12f);
#pragma unroll
        for (int j = 0; j < 8; j++) { qs[row][j0 + j] *= iq; ks[row][j0 + j] *= ik; }
    }
    __syncthreads();

    float scale = expf(fminf(logit_scale[h], 4.6051701859880914f));  // ln(100)

    // S = qn @ kn^T * scale + bias16 + mask ; thread owns row i = t/4, 16 cols
    int i = t >> 2;
    int j0 = (t & 3) * 16;
    float qr[32];
#pragma unroll
    for (int kk = 0; kk < 32; kk++) qr[kk] = qs[i][kk];
    int li = lab[i];
    const float* brow = g_bias16 + (size_t)h * 4096 + i * 64;
    float sv[16];
#pragma unroll
    for (int r = 0; r < 16; r++) {
        int j = j0 + r;
        float a = 0.f;
#pragma unroll
        for (int kk = 0; kk < 32; kk++) a = fmaf(qr[kk], ks[j][kk], a);
        a = fmaf(a, scale, brow[j]);
        if (lab[j] != li) a -= 100.f;
        sv[r] = a;
    }
    // softmax across the quad
    float mx = sv[0];
#pragma unroll
    for (int r = 1; r < 16; r++) mx = fmaxf(mx, sv[r]);
    mx = fmaxf(mx, __shfl_xor_sync(0xffffffffu, mx, 1));
    mx = fmaxf(mx, __shfl_xor_sync(0xffffffffu, mx, 2));
    float sum = 0.f;
#pragma unroll
    for (int r = 0; r < 16; r++) { sv[r] = expf(sv[r] - mx); sum += sv[r]; }
    sum += __shfl_xor_sync(0xffffffffu, sum, 1);
    sum += __shfl_xor_sync(0xffffffffu, sum, 2);
    float inv = 1.f / sum;
#pragma unroll
    for (int r = 0; r < 16; r++) Ss[i][j0 + r] = sv[r] * inv;
    __syncthreads();

    // out = P @ V ; warp handles one row, lanes cover d
#pragma unroll
    for (int r = 0; r < 8; r++) {
        int o = r * 256 + t;
        int oi = o >> 5, d = o & 31;
        float a = 0.f;
#pragma unroll
        for (int j = 0; j < 64; j++) a = fmaf(Ss[oi][j], vs[j][d], a);
        g_attnout[((size_t)win * 64 + oi) * 256 + h * 32 + d] = a;
    }
}

// ---------------- block reduction helper ----------------
__device__ __forceinline__ float block_sum_256(float v, float* sh) {
    int t = threadIdx.x;
#pragma unroll
    for (int o = 16; o > 0; o >>= 1) v += __shfl_xor_sync(0xffffffffu, v, o);
    if ((t & 31) == 0) sh[t >> 5] = v;
    __syncthreads();
    if (t < 32) {
        float r = (t < 8) ? sh[t] : 0.f;
#pragma unroll
        for (int o = 4; o > 0; o >>= 1) r += __shfl_xor_sync(0xffffffffu, r, o);
        if (t == 0) sh[0] = r;
    }
    __syncthreads();
    float r = sh[0];
    __syncthreads();
    return r;
}

// LN1: gather proj output back through window-reverse + reverse shift,
// xr = x + LN(gathered)*g + b
__global__ __launch_bounds__(256) void ln_res1_kernel(const float* __restrict__ x,
                                                      const float* __restrict__ g,
                                                      const float* __restrict__ b) {
    __shared__ float sh[8];
    int row = blockIdx.x;
    int t = threadIdx.x;
    int bb = row >> 12;
    int l = row & 4095;
    int r = l >> 6, c = l & 63;
    int rs = (r + 64 - SHIFT_) & 63, cs = (c + 64 - SHIFT_) & 63;
    int win = bb * 64 + (rs >> 3) * 8 + (cs >> 3);
    int n = (rs & 7) * 8 + (cs & 7);
    float y = g_tmp[((size_t)win * 64 + n) * 256 + t];
    float m = block_sum_256(y, sh) * (1.f / 256.f);
    float d = y - m;
    float v = block_sum_256(d * d, sh) * (1.f / 256.f);
    float o = d * rsqrtf(v + 1e-5f) * g[t] + b[t];
    g_xr[(size_t)row * 256 + t] = x[(size_t)row * 256 + t] + o;
}

// LN2: out = xr + LN(fc2_out)*g + b
__global__ __launch_bounds__(256) void ln_res2_kernel(float* __restrict__ out,
                                                      const float* __restrict__ g,
                                                      const float* __restrict__ b) {
    __shared__ float sh[8];
    int row = blockIdx.x;
    int t = threadIdx.x;
    float y = g_tmp[(size_t)row * 256 + t];
    float m = block_sum_256(y, sh) * (1.f / 256.f);
    float d = y - m;
    float v = block_sum_256(d * d, sh) * (1.f / 256.f);
    float o = d * rsqrtf(v + 1e-5f) * g[t] + b[t];
    out[(size_t)row * 256 + t] = g_xr[(size_t)row * 256 + t] + o;
}

// ---------------- launch ----------------
extern "C" void kernel_launch(void* const* d_in, const int* in_sizes, int n_in,
                              void* d_out, int out_size) {
    const float* x        = (const float*)d_in[0];
    const float* norm1_g  = (const float*)d_in[1];
    const float* norm1_b  = (const float*)d_in[2];
    const float* qkv_w    = (const float*)d_in[3];
    const float* q_bias   = (const float*)d_in[4];
    const float* v_bias   = (const float*)d_in[5];
    const float* logit_sc = (const float*)d_in[6];
    const float* cpb_w1   = (const float*)d_in[7];
    const float* cpb_b1   = (const float*)d_in[8];
    const float* cpb_w2   = (const float*)d_in[9];
    const float* proj_w   = (const float*)d_in[10];
    const float* proj_b   = (const float*)d_in[11];
    const float* norm2_g  = (const float*)d_in[12];
    const float* norm2_b  = (const float*)d_in[13];
    const float* fc1_w    = (const float*)d_in[14];
    const float* fc1_b    = (const float*)d_in[15];
    const float* fc2_w    = (const float*)d_in[16];
    const float* fc2_b    = (const float*)d_in[17];
    float* out = (float*)d_out;

    float *p_xw, *p_qkv, *p_attnout, *p_tmp, *p_xr, *p_hdn, *p_qkvb;
    cudaGetSymbolAddress((void**)&p_xw, g_xw);
    cudaGetSymbolAddress((void**)&p_qkv, g_qkv);
    cudaGetSymbolAddress((void**)&p_attnout, g_attnout);
    cudaGetSymbolAddress((void**)&p_tmp, g_tmp);
    cudaGetSymbolAddress((void**)&p_xr, g_xr);
    cudaGetSymbolAddress((void**)&p_hdn, g_hdn);
    cudaGetSymbolAddress((void**)&p_qkvb, g_qkvb);

    fill_qkvb_kernel<<<1, 768>>>(q_bias, v_bias);
    cpb_kernel<<<1, 256>>>(cpb_w1, cpb_b1, cpb_w2);
    bias16_kernel<<<(HEADS * NTOK * NTOK) / 256, 256>>>();
    gather_win_kernel<<<(M_ROWS * 64) / 256, 256>>>(x);

    // QKV GEMM: (131072 x 768) = xw(131072x256) @ qkv_w^T
    gemm_kernel<<<dim3(768 / BN, M_ROWS / BM), 256>>>(p_xw, qkv_w, p_qkvb, p_qkv, 768, 256, 0);

    // window attention
    attn_kernel<<<(M_ROWS / NTOK) * HEADS, 256>>>(logit_sc);

    // proj
    gemm_kernel<<<dim3(256 / BN, M_ROWS / BM), 256>>>(p_attnout, proj_w, proj_b, p_tmp, 256, 256, 0);

    // LN1 + residual (with window reverse gather)
    ln_res1_kernel<<<M_ROWS, 256>>>(x, norm1_g, norm1_b);

    // MLP
    gemm_kernel<<<dim3(1024 / BN, M_ROWS / BM), 256>>>(p_xr, fc1_w, fc1_b, p_hdn, 1024, 256, 1);
    gemm_kernel<<<dim3(256 / BN, M_ROWS / BM), 256>>>(p_hdn, fc2_w, fc2_b, p_tmp, 256, 1024, 0);

    // LN2 + residual -> out
    ln_res2_kernel<<<M_ROWS, 256>>>(out, norm2_g, norm2_b);
}

// round 3
// speedup vs baseline: 1.7838x; 1.7838x over previous
#include <cuda_runtime.h>
#include <math.h>
#include <stdint.h>

#define DIMC 256
#define HEADS 8
#define HEAD_DIM 32
#define WSZ 8
#define NTOK 64            // tokens per window (8x8)
#define BATCH 32
#define HH 64
#define WWID 64
#define LTOK (HH*WWID)     // 4096
#define M_ROWS (BATCH*LTOK)  // 131072
#define SHIFT_ 4

// ---------------- scratch (static device globals; no allocation) ----------------
static __device__ float g_xw[(size_t)M_ROWS * DIMC];          // 134 MB windowed x
static __device__ float g_qkv[(size_t)M_ROWS * 3 * DIMC];     // 402 MB
static __device__ float g_attnout[(size_t)M_ROWS * DIMC];     // 134 MB
static __device__ float g_tmp[(size_t)M_ROWS * DIMC];         // 134 MB (proj out, then fc2 out)
static __device__ float g_xr[(size_t)M_ROWS * DIMC];          // 134 MB
static __device__ float g_hdn[(size_t)M_ROWS * 4 * DIMC];     // 537 MB
static __device__ float g_cpb[225 * HEADS];
static __device__ float g_bias16[HEADS * NTOK * NTOK];
static __device__ float g_qkvb[3 * DIMC];

// ---------------- tiny setup kernels ----------------
__global__ void fill_qkvb_kernel(const float* __restrict__ q_bias,
                                 const float* __restrict__ v_bias) {
    int t = threadIdx.x;  // 768
    float v;
    if (t < 256)      v = q_bias[t];
    else if (t < 512) v = 0.f;
    else              v = v_bias[t - 512];
    g_qkvb[t] = v;
}

// CPB MLP: coords(225,2) -> relu(512) -> (heads)
__global__ void cpb_kernel(const float* __restrict__ w1, const float* __restrict__ b1,
                           const float* __restrict__ w2) {
    int i = threadIdx.x;
    if (i >= 225) return;
    float a  = (float)(i / 15) - 7.f;
    float bb = (float)(i % 15) - 7.f;
    float f0 = a  * (8.f / 7.f);
    float f1 = bb * (8.f / 7.f);
    f0 = copysignf(log2f(fabsf(f0) + 1.f) * (1.f / 3.f), f0);
    f1 = copysignf(log2f(fabsf(f1) + 1.f) * (1.f / 3.f), f1);
    float acc[HEADS];
#pragma unroll
    for (int h = 0; h < HEADS; h++) acc[h] = 0.f;
    for (int u = 0; u < 512; u++) {
        float hu = fmaf(w1[2 * u], f0, fmaf(w1[2 * u + 1], f1, b1[u]));
        hu = fmaxf(hu, 0.f);
#pragma unroll
        for (int h = 0; h < HEADS; h++) acc[h] = fmaf(hu, w2[h * 512 + u], acc[h]);
    }
#pragma unroll
    for (int h = 0; h < HEADS; h++) g_cpb[i * HEADS + h] = acc[h];
}

// Expand to 16*sigmoid(rpb) table: (heads, 64, 64)
__global__ void bias16_kernel() {
    int gid = blockIdx.x * blockDim.x + threadIdx.x;  // 8*4096
    if (gid >= HEADS * NTOK * NTOK) return;
    int h = gid >> 12;
    int ij = gid & 4095;
    int i = ij >> 6, j = ij & 63;
    int dr = (i >> 3) - (j >> 3);
    int dc = (i & 7) - (j & 7);
    int idx = (dr + 7) * 15 + (dc + 7);
    float x = g_cpb[idx * HEADS + h];
    g_bias16[gid] = 16.f / (1.f + expf(-x));
}

// ---------------- shift + window partition gather ----------------
__global__ void gather_win_kernel(const float* __restrict__ x) {
    int t = blockIdx.x * blockDim.x + threadIdx.x;  // over M_ROWS*64 float4
    int m = t >> 6, c4 = t & 63;
    int win = m >> 6, n = m & 63;
    int b = win >> 6, wr = (win >> 3) & 7, wc = win & 7;
    int ir = n >> 3, ic = n & 7;
    int r = (wr * 8 + ir + SHIFT_) & 63;
    int c = (wc * 8 + ic + SHIFT_) & 63;
    const float4* src = (const float4*)(x + ((size_t)b * LTOK + r * 64 + c) * DIMC);
    ((float4*)(g_xw + (size_t)m * DIMC))[c4] = src[c4];
}

// ---------------- tf32 tensor-core GEMM: C[M,N] = A[M,K] @ W[N,K]^T + bias ----------------
// block tile 128x64, 8 warps each 32x32 (2x4 m16n8k8 tiles), BK=32
#define TBM 128
#define TBN 64
#define TBK 32

__device__ __forceinline__ float to_tf32(float x) {
    uint32_t o;
    asm("cvt.rna.tf32.f32 %0, %1;" : "=r"(o) : "f"(x));
    return __uint_as_float(o);
}

__global__ __launch_bounds__(256) void mma_gemm_kernel(
    const float* __restrict__ A, const float* __restrict__ W,
    const float* __restrict__ bias, float* __restrict__ C,
    int N, int K, int gelu) {
    __shared__ float As[TBM][TBK + 4];
    __shared__ float Ws[TBN][TBK + 4];
    int tid = threadIdx.x;
    int wid = tid >> 5, lane = tid & 31;
    int wm = wid >> 1, wn = wid & 1;       // warp tile origin (wm*32, wn*32)
    int brow = blockIdx.y * TBM, bcol = blockIdx.x * TBN;
    int lq = lane >> 2;        // 0..7
    int lr = lane & 3;         // 0..3

    float acc[2][4][4];
#pragma unroll
    for (int mi = 0; mi < 2; mi++)
#pragma unroll
        for (int ni = 0; ni < 4; ni++)
#pragma unroll
            for (int r = 0; r < 4; r++) acc[mi][ni][r] = 0.f;

    for (int k0 = 0; k0 < K; k0 += TBK) {
        // load A tile: 128x32 = 1024 float4 / 256 thr = 4 each
#pragma unroll
        for (int f = 0; f < 4; f++) {
            int idx = tid + f * 256;
            int r = idx >> 3, c4 = (idx & 7) * 4;
            float4 v = *(const float4*)(A + (size_t)(brow + r) * K + k0 + c4);
            As[r][c4 + 0] = to_tf32(v.x); As[r][c4 + 1] = to_tf32(v.y);
            As[r][c4 + 2] = to_tf32(v.z); As[r][c4 + 3] = to_tf32(v.w);
        }
        // load W tile: 64x32 = 512 float4 / 256 thr = 2 each
#pragma unroll
        for (int f = 0; f < 2; f++) {
            int idx = tid + f * 256;
            int r = idx >> 3, c4 = (idx & 7) * 4;
            float4 v = *(const float4*)(W + (size_t)(bcol + r) * K + k0 + c4);
            Ws[r][c4 + 0] = to_tf32(v.x); Ws[r][c4 + 1] = to_tf32(v.y);
            Ws[r][c4 + 2] = to_tf32(v.z); Ws[r][c4 + 3] = to_tf32(v.w);
        }
        __syncthreads();

#pragma unroll
        for (int kk = 0; kk < TBK; kk += 8) {
            uint32_t afr[2][4];
#pragma unroll
            for (int mi = 0; mi < 2; mi++) {
                int rb = wm * 32 + mi * 16;
                afr[mi][0] = *(const uint32_t*)&As[rb + lq][kk + lr];
                afr[mi][1] = *(const uint32_t*)&As[rb + lq + 8][kk + lr];
                afr[mi][2] = *(const uint32_t*)&As[rb + lq][kk + 4 + lr];
                afr[mi][3] = *(const uint32_t*)&As[rb + lq + 8][kk + 4 + lr];
            }
            uint32_t bfr[4][2];
#pragma unroll
            for (int ni = 0; ni < 4; ni++) {
                int nb = wn * 32 + ni * 8;
                bfr[ni][0] = *(const uint32_t*)&Ws[nb + lq][kk + lr];
                bfr[ni][1] = *(const uint32_t*)&Ws[nb + lq][kk + 4 + lr];
            }
#pragma unroll
            for (int mi = 0; mi < 2; mi++)
#pragma unroll
                for (int ni = 0; ni < 4; ni++) {
                    asm volatile(
                        "mma.sync.aligned.m16n8k8.row.col.f32.tf32.tf32.f32 "
                        "{%0,%1,%2,%3}, {%4,%5,%6,%7}, {%8,%9}, {%0,%1,%2,%3};"
                        : "+f"(acc[mi][ni][0]), "+f"(acc[mi][ni][1]),
                          "+f"(acc[mi][ni][2]), "+f"(acc[mi][ni][3])
                        : "r"(afr[mi][0]), "r"(afr[mi][1]),
                          "r"(afr[mi][2]), "r"(afr[mi][3]),
                          "r"(bfr[ni][0]), "r"(bfr[ni][1]));
                }
        }
        __syncthreads();
    }

    // epilogue: bias (+ optional exact GELU), write float2 pairs
#pragma unroll
    for (int mi = 0; mi < 2; mi++) {
#pragma unroll
        for (int ni = 0; ni < 4; ni++) {
            int col = bcol + wn * 32 + ni * 8 + lr * 2;
            float b0 = bias[col], b1 = bias[col + 1];
            int r0 = brow + wm * 32 + mi * 16 + lq;
            float v0 = acc[mi][ni][0] + b0;
            float v1 = acc[mi][ni][1] + b1;
            float v2 = acc[mi][ni][2] + b0;
            float v3 = acc[mi][ni][3] + b1;
            if (gelu) {
                v0 = 0.5f * v0 * (1.f + erff(v0 * 0.70710678118654752f));
                v1 = 0.5f * v1 * (1.f + erff(v1 * 0.70710678118654752f));
                v2 = 0.5f * v2 * (1.f + erff(v2 * 0.70710678118654752f));
                v3 = 0.5f * v3 * (1.f + erff(v3 * 0.70710678118654752f));
            }
            *(float2*)(C + (size_t)r0 * N + col) = make_float2(v0, v1);
            *(float2*)(C + (size_t)(r0 + 8) * N + col) = make_float2(v2, v3);
        }
    }
}

// ---------------- fused window attention: one block per (window, head) ----------------
__global__ __launch_bounds__(256) void attn_kernel(const float* __restrict__ logit_scale) {
    __shared__ float qs[NTOK][33];
    __shared__ float ks[NTOK][33];
    __shared__ float vs[NTOK][33];
    __shared__ float Ss[NTOK][65];
    __shared__ int lab[NTOK];

    int blk = blockIdx.x;
    int win = blk >> 3, h = blk & 7;
    int t = threadIdx.x;

    size_t base = (size_t)win * NTOK * 768;
#pragma unroll
    for (int f = t; f < 512; f += 256) {
        int n = f >> 3, d4 = (f & 7) * 4;
        const float* rowp = g_qkv + base + (size_t)n * 768 + h * 32 + d4;
        float4 q4 = *(const float4*)(rowp);
        float4 k4 = *(const float4*)(rowp + 256);
        float4 v4 = *(const float4*)(rowp + 512);
        qs[n][d4] = q4.x; qs[n][d4 + 1] = q4.y; qs[n][d4 + 2] = q4.z; qs[n][d4 + 3] = q4.w;
        ks[n][d4] = k4.x; ks[n][d4 + 1] = k4.y; ks[n][d4 + 2] = k4.z; ks[n][d4 + 3] = k4.w;
        vs[n][d4] = v4.x; vs[n][d4 + 1] = v4.y; vs[n][d4 + 2] = v4.z; vs[n][d4 + 3] = v4.w;
    }
    if (t < NTOK) {
        int wr = (win >> 3) & 7, wc = win & 7;
        int rs = wr * 8 + (t >> 3), cs = wc * 8 + (t & 7);
        int lr = rs < 56 ? 0 : (rs < 60 ? 1 : 2);
        int lc = cs < 56 ? 0 : (cs < 60 ? 1 : 2);
        lab[t] = lr * 3 + lc;
    }
    __syncthreads();

    // cosine-normalize q,k rows: 4 threads per row, 8 elems each
    {
        int row = t >> 2, j0 = (t & 3) * 8;
        float sq = 0.f, sk = 0.f;
#pragma unroll
        for (int j = 0; j < 8; j++) {
            float a = qs[row][j0 + j]; sq = fmaf(a, a, sq);
            float b = ks[row][j0 + j]; sk = fmaf(b, b, sk);
        }
        sq += __shfl_xor_sync(0xffffffffu, sq, 1);
        sq += __shfl_xor_sync(0xffffffffu, sq, 2);
        sk += __shfl_xor_sync(0xffffffffu, sk, 1);
        sk += __shfl_xor_sync(0xffffffffu, sk, 2);
        float iq = 1.f / fmaxf(sqrtf(sq), 1e-12f);
        float ik = 1.f / fmaxf(sqrtf(sk), 1e-12f);
#pragma unroll
        for (int j = 0; j < 8; j++) { qs[row][j0 + j] *= iq; ks[row][j0 + j] *= ik; }
    }
    __syncthreads();

    float scale = expf(fminf(logit_scale[h], 4.6051701859880914f));  // ln(100)

    // S = qn @ kn^T * scale + bias16 + mask ; thread owns row i = t/4, 16 cols
    int i = t >> 2;
    int j0 = (t & 3) * 16;
    float qr[32];
#pragma unroll
    for (int kk = 0; kk < 32; kk++) qr[kk] = qs[i][kk];
    int li = lab[i];
    const float* brow = g_bias16 + (size_t)h * 4096 + i * 64;
    float sv[16];
#pragma unroll
    for (int r = 0; r < 16; r++) {
        int j = j0 + r;
        float a = 0.f;
#pragma unroll
        for (int kk = 0; kk < 32; kk++) a = fmaf(qr[kk], ks[j][kk], a);
        a = fmaf(a, scale, brow[j]);
        if (lab[j] != li) a -= 100.f;
        sv[r] = a;
    }
    // softmax across the quad
    float mx = sv[0];
#pragma unroll
    for (int r = 1; r < 16; r++) mx = fmaxf(mx, sv[r]);
    mx = fmaxf(mx, __shfl_xor_sync(0xffffffffu, mx, 1));
    mx = fmaxf(mx, __shfl_xor_sync(0xffffffffu, mx, 2));
    float sum = 0.f;
#pragma unroll
    for (int r = 0; r < 16; r++) { sv[r] = expf(sv[r] - mx); sum += sv[r]; }
    sum += __shfl_xor_sync(0xffffffffu, sum, 1);
    sum += __shfl_xor_sync(0xffffffffu, sum, 2);
    float inv = 1.f / sum;
#pragma unroll
    for (int r = 0; r < 16; r++) Ss[i][j0 + r] = sv[r] * inv;
    __syncthreads();

    // out = P @ V ; warp handles one row, lanes cover d
#pragma unroll
    for (int r = 0; r < 8; r++) {
        int o = r * 256 + t;
        int oi = o >> 5, d = o & 31;
        float a = 0.f;
#pragma unroll
        for (int j = 0; j < 64; j++) a = fmaf(Ss[oi][j], vs[j][d], a);
        g_attnout[((size_t)win * 64 + oi) * 256 + h * 32 + d] = a;
    }
}

// ---------------- block reduction helper ----------------
__device__ __forceinline__ float block_sum_256(float v, float* sh) {
    int t = threadIdx.x;
#pragma unroll
    for (int o = 16; o > 0; o >>= 1) v += __shfl_xor_sync(0xffffffffu, v, o);
    if ((t & 31) == 0) sh[t >> 5] = v;
    __syncthreads();
    if (t < 32) {
        float r = (t < 8) ? sh[t] : 0.f;
#pragma unroll
        for (int o = 4; o > 0; o >>= 1) r += __shfl_xor_sync(0xffffffffu, r, o);
        if (t == 0) sh[0] = r;
    }
    __syncthreads();
    float r = sh[0];
    __syncthreads();
    return r;
}

// LN1: gather proj output back through window-reverse + reverse shift,
// xr = x + LN(gathered)*g + b
__global__ __launch_bounds__(256) void ln_res1_kernel(const float* __restrict__ x,
                                                      const float* __restrict__ g,
                                                      const float* __restrict__ b) {
    __shared__ float sh[8];
    int row = blockIdx.x;
    int t = threadIdx.x;
    int bb = row >> 12;
    int l = row & 4095;
    int r = l >> 6, c = l & 63;
    int rs = (r + 64 - SHIFT_) & 63, cs = (c + 64 - SHIFT_) & 63;
    int win = bb * 64 + (rs >> 3) * 8 + (cs >> 3);
    int n = (rs & 7) * 8 + (cs & 7);
    float y = g_tmp[((size_t)win * 64 + n) * 256 + t];
    float m = block_sum_256(y, sh) * (1.f / 256.f);
    float d = y - m;
    float v = block_sum_256(d * d, sh) * (1.f / 256.f);
    float o = d * rsqrtf(v + 1e-5f) * g[t] + b[t];
    g_xr[(size_t)row * 256 + t] = x[(size_t)row * 256 + t] + o;
}

// LN2: out = xr + LN(fc2_out)*g + b
__global__ __launch_bounds__(256) void ln_res2_kernel(float* __restrict__ out,
                                                      const float* __restrict__ g,
                                                      const float* __restrict__ b) {
    __shared__ float sh[8];
    int row = blockIdx.x;
    int t = threadIdx.x;
    float y = g_tmp[(size_t)row * 256 + t];
    float m = block_sum_256(y, sh) * (1.f / 256.f);
    float d = y - m;
    float v = block_sum_256(d * d, sh) * (1.f / 256.f);
    float o = d * rsqrtf(v + 1e-5f) * g[t] + b[t];
    out[(size_t)row * 256 + t] = g_xr[(size_t)row * 256 + t] + o;
}

// ---------------- launch ----------------
extern "C" void kernel_launch(void* const* d_in, const int* in_sizes, int n_in,
                              void* d_out, int out_size) {
    const float* x        = (const float*)d_in[0];
    const float* norm1_g  = (const float*)d_in[1];
    const float* norm1_b  = (const float*)d_in[2];
    const float* qkv_w    = (const float*)d_in[3];
    const float* q_bias   = (const float*)d_in[4];
    const float* v_bias   = (const float*)d_in[5];
    const float* logit_sc = (const float*)d_in[6];
    const float* cpb_w1   = (const float*)d_in[7];
    const float* cpb_b1   = (const float*)d_in[8];
    const float* cpb_w2   = (const float*)d_in[9];
    const float* proj_w   = (const float*)d_in[10];
    const float* proj_b   = (const float*)d_in[11];
    const float* norm2_g  = (const float*)d_in[12];
    const float* norm2_b  = (const float*)d_in[13];
    const float* fc1_w    = (const float*)d_in[14];
    const float* fc1_b    = (const float*)d_in[15];
    const float* fc2_w    = (const float*)d_in[16];
    const float* fc2_b    = (const float*)d_in[17];
    float* out = (float*)d_out;

    float *p_xw, *p_qkv, *p_attnout, *p_tmp, *p_xr, *p_hdn, *p_qkvb;
    cudaGetSymbolAddress((void**)&p_xw, g_xw);
    cudaGetSymbolAddress((void**)&p_qkv, g_qkv);
    cudaGetSymbolAddress((void**)&p_attnout, g_attnout);
    cudaGetSymbolAddress((void**)&p_tmp, g_tmp);
    cudaGetSymbolAddress((void**)&p_xr, g_xr);
    cudaGetSymbolAddress((void**)&p_hdn, g_hdn);
    cudaGetSymbolAddress((void**)&p_qkvb, g_qkvb);

    fill_qkvb_kernel<<<1, 768>>>(q_bias, v_bias);
    cpb_kernel<<<1, 256>>>(cpb_w1, cpb_b1, cpb_w2);
    bias16_kernel<<<(HEADS * NTOK * NTOK) / 256, 256>>>();
    gather_win_kernel<<<(M_ROWS * 64) / 256, 256>>>(x);

    // QKV GEMM: (131072 x 768) = xw(131072x256) @ qkv_w^T
    mma_gemm_kernel<<<dim3(768 / TBN, M_ROWS / TBM), 256>>>(p_xw, qkv_w, p_qkvb, p_qkv, 768, 256, 0);

    // window attention
    attn_kernel<<<(M_ROWS / NTOK) * HEADS, 256>>>(logit_sc);

    // proj
    mma_gemm_kernel<<<dim3(256 / TBN, M_ROWS / TBM), 256>>>(p_attnout, proj_w, proj_b, p_tmp, 256, 256, 0);

    // LN1 + residual (with window reverse gather)
    ln_res1_kernel<<<M_ROWS, 256>>>(x, norm1_g, norm1_b);

    // MLP
    mma_gemm_kernel<<<dim3(1024 / TBN, M_ROWS / TBM), 256>>>(p_xr, fc1_w, fc1_b, p_hdn, 1024, 256, 1);
    mma_gemm_kernel<<<dim3(256 / TBN, M_ROWS / TBM), 256>>>(p_hdn, fc2_w, fc2_b, p_tmp, 256, 1024, 0);

    // LN2 + residual -> out
    ln_res2_kernel<<<M_ROWS, 256>>>(out, norm2_g, norm2_b);
}

// round 4
// speedup vs baseline: 2.4343x; 1.3646x over previous
#include <cuda_runtime.h>
#include <math.h>
#include <stdint.h>

#define DIMC 256
#define HEADS 8
#define NTOK 64
#define BATCH 32
#define LTOK 4096
#define M_ROWS (BATCH*LTOK)  // 131072
#define SHIFT_ 4

// ---------------- scratch ----------------
static __device__ float g_qkv[(size_t)M_ROWS * 3 * DIMC];
static __device__ float g_attnout[(size_t)M_ROWS * DIMC];
static __device__ float g_tmp[(size_t)M_ROWS * DIMC];
static __device__ float g_xr[(size_t)M_ROWS * DIMC];
static __device__ float g_hdn[(size_t)M_ROWS * 4 * DIMC];
static __device__ float g_cpb[225 * HEADS];
static __device__ float g_bias16[HEADS * NTOK * NTOK];
static __device__ float g_qkvb[3 * DIMC];

// ---------------- tiny setup kernels ----------------
__global__ void fill_qkvb_kernel(const float* __restrict__ q_bias,
                                 const float* __restrict__ v_bias) {
    int t = threadIdx.x;
    float v;
    if (t < 256)      v = q_bias[t];
    else if (t < 512) v = 0.f;
    else              v = v_bias[t - 512];
    g_qkvb[t] = v;
}

__global__ void cpb_kernel(const float* __restrict__ w1, const float* __restrict__ b1,
                           const float* __restrict__ w2) {
    int i = threadIdx.x;
    if (i >= 225) return;
    float a  = (float)(i / 15) - 7.f;
    float bb = (float)(i % 15) - 7.f;
    float f0 = a  * (8.f / 7.f);
    float f1 = bb * (8.f / 7.f);
    f0 = copysignf(log2f(fabsf(f0) + 1.f) * (1.f / 3.f), f0);
    f1 = copysignf(log2f(fabsf(f1) + 1.f) * (1.f / 3.f), f1);
    float acc[HEADS];
#pragma unroll
    for (int h = 0; h < HEADS; h++) acc[h] = 0.f;
    for (int u = 0; u < 512; u++) {
        float hu = fmaf(w1[2 * u], f0, fmaf(w1[2 * u + 1], f1, b1[u]));
        hu = fmaxf(hu, 0.f);
#pragma unroll
        for (int h = 0; h < HEADS; h++) acc[h] = fmaf(hu, w2[h * 512 + u], acc[h]);
    }
#pragma unroll
    for (int h = 0; h < HEADS; h++) g_cpb[i * HEADS + h] = acc[h];
}

__global__ void bias16_kernel() {
    int gid = blockIdx.x * blockDim.x + threadIdx.x;
    if (gid >= HEADS * NTOK * NTOK) return;
    int h = gid >> 12;
    int ij = gid & 4095;
    int i = ij >> 6, j = ij & 63;
    int dr = (i >> 3) - (j >> 3);
    int dc = (i & 7) - (j & 7);
    int idx = (dr + 7) * 15 + (dc + 7);
    float x = g_cpb[idx * HEADS + h];
    g_bias16[gid] = 16.f / (1.f + expf(-x));
}

// ---------------- tf32 tensor-core GEMM, cp.async double-buffered ----------------
// C[M,N] = A[M,K] @ W[N,K]^T + bias.  Tile 128x128xBK16, 8 warps (2x4), warp 64x32.
#define TBM 128
#define TBN 128
#define TBK 16
#define ROWF (TBK + 4)          // 20 floats padded row
#define BUFB (TBM * ROWF * 4)   // 10240 bytes per buffer

__device__ __forceinline__ uint32_t tf32u(float x) {
    uint32_t o;
    asm("cvt.rna.tf32.f32 %0, %1;" : "=r"(o) : "f"(x));
    return o;
}

__device__ __forceinline__ size_t qkv_src_row(int m) {
    int win = m >> 6, n = m & 63;
    int b = win >> 6, wr = (win >> 3) & 7, wc = win & 7;
    int r = (wr * 8 + (n >> 3) + SHIFT_) & 63;
    int c = (wc * 8 + (n & 7) + SHIFT_) & 63;
    return ((size_t)b << 12) + (size_t)(r * 64 + c);
}

#define CP16(sm, gp) asm volatile("cp.async.cg.shared.global [%0], [%1], 16;" :: "r"(sm), "l"(gp))

__global__ __launch_bounds__(256, 2) void mma_gemm_kernel(
    const float* __restrict__ A, const float* __restrict__ W,
    const float* __restrict__ bias, float* __restrict__ C,
    int N, int K, int gelu, int gatherA) {
    __shared__ float As[2][TBM][ROWF];
    __shared__ float Ws[2][TBN][ROWF];
    int tid = threadIdx.x;
    int wid = tid >> 5, lane = tid & 31;
    int wm = wid >> 2, wn = wid & 3;       // warp tile origin (wm*64, wn*32)
    int brow = blockIdx.y * TBM, bcol = blockIdx.x * TBN;
    int lq = lane >> 2, lr = lane & 3;

    // load assignment: 512 16B-chunks per tile; thread does chunk tid and tid+256
    int r0 = tid >> 2, c0 = (tid & 3) * 4;
    const float *aptr0, *aptr1;
    if (gatherA) {
        aptr0 = A + qkv_src_row(brow + r0) * 256 + c0;
        aptr1 = A + qkv_src_row(brow + r0 + 64) * 256 + c0;
    } else {
        aptr0 = A + (size_t)(brow + r0) * K + c0;
        aptr1 = A + (size_t)(brow + r0 + 64) * K + c0;
    }
    const float* wptr0 = W + (size_t)(bcol + r0) * K + c0;
    const float* wptr1 = W + (size_t)(bcol + r0 + 64) * K + c0;

    uint32_t sA = (uint32_t)__cvta_generic_to_shared(&As[0][0][0]) + (r0 * ROWF + c0) * 4;
    uint32_t sW = (uint32_t)__cvta_generic_to_shared(&Ws[0][0][0]) + (r0 * ROWF + c0) * 4;
    const uint32_t rowoff = 64 * ROWF * 4;

    float acc[4][4][4];
#pragma unroll
    for (int mi = 0; mi < 4; mi++)
#pragma unroll
        for (int ni = 0; ni < 4; ni++)
#pragma unroll
            for (int r = 0; r < 4; r++) acc[mi][ni][r] = 0.f;

    int KT = K / TBK;
    // prime buffer 0
    CP16(sA, aptr0); CP16(sA + rowoff, aptr1);
    CP16(sW, wptr0); CP16(sW + rowoff, wptr1);
    asm volatile("cp.async.commit_group;" ::: "memory");

    int buf = 0;
    for (int kt = 0; kt < KT; kt++) {
        asm volatile("cp.async.wait_group 0;" ::: "memory");
        __syncthreads();
        if (kt + 1 < KT) {
            int k0 = (kt + 1) * TBK;
            uint32_t bo = (buf ^ 1) * (uint32_t)BUFB;
            CP16(sA + bo, aptr0 + k0); CP16(sA + bo + rowoff, aptr1 + k0);
            CP16(sW + bo, wptr0 + k0); CP16(sW + bo + rowoff, wptr1 + k0);
            asm volatile("cp.async.commit_group;" ::: "memory");
        }
#pragma unroll
        for (int kk = 0; kk < TBK; kk += 8) {
            uint32_t af[4][4];
#pragma unroll
            for (int mi = 0; mi < 4; mi++) {
                int rb = wm * 64 + mi * 16 + lq;
                af[mi][0] = tf32u(As[buf][rb][kk + lr]);
                af[mi][1] = tf32u(As[buf][rb + 8][kk + lr]);
                af[mi][2] = tf32u(As[buf][rb][kk + 4 + lr]);
                af[mi][3] = tf32u(As[buf][rb + 8][kk + 4 + lr]);
            }
            uint32_t bf[4][2];
#pragma unroll
            for (int ni = 0; ni < 4; ni++) {
                int nb = wn * 32 + ni * 8 + lq;
                bf[ni][0] = tf32u(Ws[buf][nb][kk + lr]);
                bf[ni][1] = tf32u(Ws[buf][nb][kk + 4 + lr]);
            }
#pragma unroll
            for (int mi = 0; mi < 4; mi++)
#pragma unroll
                for (int ni = 0; ni < 4; ni++) {
                    asm volatile(
                        "mma.sync.aligned.m16n8k8.row.col.f32.tf32.tf32.f32 "
                        "{%0,%1,%2,%3}, {%4,%5,%6,%7}, {%8,%9}, {%0,%1,%2,%3};"
                        : "+f"(acc[mi][ni][0]), "+f"(acc[mi][ni][1]),
                          "+f"(acc[mi][ni][2]), "+f"(acc[mi][ni][3])
                        : "r"(af[mi][0]), "r"(af[mi][1]), "r"(af[mi][2]), "r"(af[mi][3]),
                          "r"(bf[ni][0]), "r"(bf[ni][1]));
                }
        }
        buf ^= 1;
    }

#pragma unroll
    for (int mi = 0; mi < 4; mi++) {
#pragma unroll
        for (int ni = 0; ni < 4; ni++) {
            int col = bcol + wn * 32 + ni * 8 + lr * 2;
            float b0 = bias[col], b1 = bias[col + 1];
            int rr = brow + wm * 64 + mi * 16 + lq;
            float v0 = acc[mi][ni][0] + b0;
            float v1 = acc[mi][ni][1] + b1;
            float v2 = acc[mi][ni][2] + b0;
            float v3 = acc[mi][ni][3] + b1;
            if (gelu) {
                v0 = 0.5f * v0 * (1.f + erff(v0 * 0.70710678118654752f));
                v1 = 0.5f * v1 * (1.f + erff(v1 * 0.70710678118654752f));
                v2 = 0.5f * v2 * (1.f + erff(v2 * 0.70710678118654752f));
                v3 = 0.5f * v3 * (1.f + erff(v3 * 0.70710678118654752f));
            }
            *(float2*)(C + (size_t)rr * N + col) = make_float2(v0, v1);
            *(float2*)(C + (size_t)(rr + 8) * N + col) = make_float2(v2, v3);
        }
    }
}

// ---------------- fused window attention, register-blocked ----------------
__global__ __launch_bounds__(256) void attn_kernel(const float* __restrict__ logit_scale) {
    __shared__ float qs[64][36];
    __shared__ float ksT[32][68];   // transposed: [d][token]
    __shared__ float vs[64][36];
    __shared__ float Ss[64][68];
    __shared__ int lab[64];

    int blk = blockIdx.x;
    int win = blk >> 3, h = blk & 7;
    int t = threadIdx.x;

    size_t base = (size_t)win * 64 * 768;
#pragma unroll
    for (int f = t; f < 512; f += 256) {
        int n = f >> 3, d4 = (f & 7) * 4;
        const float* rowp = g_qkv + base + (size_t)n * 768 + h * 32 + d4;
        float4 q4 = *(const float4*)(rowp);
        float4 k4 = *(const float4*)(rowp + 256);
        float4 v4 = *(const float4*)(rowp + 512);
        *(float4*)&qs[n][d4] = q4;
        ksT[d4 + 0][n] = k4.x; ksT[d4 + 1][n] = k4.y;
        ksT[d4 + 2][n] = k4.z; ksT[d4 + 3][n] = k4.w;
        *(float4*)&vs[n][d4] = v4;
    }
    if (t < 64) {
        int wr = (win >> 3) & 7, wc = win & 7;
        int rs = wr * 8 + (t >> 3), cs = wc * 8 + (t & 7);
        int lr2 = rs < 56 ? 0 : (rs < 60 ? 1 : 2);
        int lc2 = cs < 56 ? 0 : (cs < 60 ? 1 : 2);
        lab[t] = lr2 * 3 + lc2;
    }
    __syncthreads();

    // normalize q rows (4 threads/row)
    {
        int row = t >> 2, j0 = (t & 3) * 8;
        float sq = 0.f;
#pragma unroll
        for (int j = 0; j < 8; j++) { float a = qs[row][j0 + j]; sq = fmaf(a, a, sq); }
        sq += __shfl_xor_sync(0xffffffffu, sq, 1);
        sq += __shfl_xor_sync(0xffffffffu, sq, 2);
        float iq = 1.f / fmaxf(sqrtf(sq), 1e-12f);
#pragma unroll
        for (int j = 0; j < 8; j++) qs[row][j0 + j] *= iq;
    }
    // normalize k columns of ksT (4 threads/token)
    {
        int tok = t >> 2, d0 = (t & 3) * 8;
        float sk = 0.f;
#pragma unroll
        for (int j = 0; j < 8; j++) { float b = ksT[d0 + j][tok]; sk = fmaf(b, b, sk); }
        sk += __shfl_xor_sync(0xffffffffu, sk, 1);
        sk += __shfl_xor_sync(0xffffffffu, sk, 2);
        float ik = 1.f / fmaxf(sqrtf(sk), 1e-12f);
#pragma unroll
        for (int j = 0; j < 8; j++) ksT[d0 + j][tok] *= ik;
    }
    __syncthreads();

    float scale = expf(fminf(logit_scale[h], 4.6051701859880914f));

    // S phase: thread (ti,tj) owns rows i0..i0+3, cols j0..j0+3
    int ti = t >> 4, tj = t & 15;
    int i0 = ti * 4, j0 = tj * 4;
    float sv[4][4];
#pragma unroll
    for (int r = 0; r < 4; r++)
#pragma unroll
        for (int c = 0; c < 4; c++) sv[r][c] = 0.f;

#pragma unroll
    for (int kk = 0; kk < 32; kk++) {
        float4 kq = *(const float4*)&ksT[kk][j0];
        float qr[4];
#pragma unroll
        for (int r = 0; r < 4; r++) qr[r] = qs[i0 + r][kk];
#pragma unroll
        for (int r = 0; r < 4; r++) {
            sv[r][0] = fmaf(qr[r], kq.x, sv[r][0]);
            sv[r][1] = fmaf(qr[r], kq.y, sv[r][1]);
            sv[r][2] = fmaf(qr[r], kq.z, sv[r][2]);
            sv[r][3] = fmaf(qr[r], kq.w, sv[r][3]);
        }
    }

    int li[4], lj[4];
#pragma unroll
    for (int r = 0; r < 4; r++) li[r] = lab[i0 + r];
#pragma unroll
    for (int c = 0; c < 4; c++) lj[c] = lab[j0 + c];
    const float* btab = g_bias16 + (size_t)h * 4096;

    float mx[4], sum[4];
#pragma unroll
    for (int r = 0; r < 4; r++) {
        float4 b4 = *(const float4*)(btab + (i0 + r) * 64 + j0);
        sv[r][0] = fmaf(sv[r][0], scale, b4.x) + ((lj[0] != li[r]) ? -100.f : 0.f);
        sv[r][1] = fmaf(sv[r][1], scale, b4.y) + ((lj[1] != li[r]) ? -100.f : 0.f);
        sv[r][2] = fmaf(sv[r][2], scale, b4.z) + ((lj[2] != li[r]) ? -100.f : 0.f);
        sv[r][3] = fmaf(sv[r][3], scale, b4.w) + ((lj[3] != li[r]) ? -100.f : 0.f);
        float m = fmaxf(fmaxf(sv[r][0], sv[r][1]), fmaxf(sv[r][2], sv[r][3]));
#pragma unroll
        for (int o = 1; o < 16; o <<= 1) m = fmaxf(m, __shfl_xor_sync(0xffffffffu, m, o));
        mx[r] = m;
        float s = 0.f;
#pragma unroll
        for (int c = 0; c < 4; c++) { sv[r][c] = expf(sv[r][c] - m); s += sv[r][c]; }
#pragma unroll
        for (int o = 1; o < 16; o <<= 1) s += __shfl_xor_sync(0xffffffffu, s, o);
        sum[r] = s;
    }
#pragma unroll
    for (int r = 0; r < 4; r++) {
        float inv = 1.f / sum[r];
        float4 p = make_float4(sv[r][0] * inv, sv[r][1] * inv, sv[r][2] * inv, sv[r][3] * inv);
        *(float4*)&Ss[i0 + r][j0] = p;
    }
    __syncthreads();

    // PV phase: thread owns 2 rows x 4 d-cols
    int tr = t >> 3, td = t & 7;
    int ip = tr * 2, d0 = td * 4;
    float po[2][4];
#pragma unroll
    for (int r = 0; r < 2; r++)
#pragma unroll
        for (int c = 0; c < 4; c++) po[r][c] = 0.f;

#pragma unroll
    for (int j4 = 0; j4 < 16; j4++) {
        float4 s4[2];
#pragma unroll
        for (int r = 0; r < 2; r++) s4[r] = *(const float4*)&Ss[ip + r][j4 * 4];
        float4 v4[4];
#pragma unroll
        for (int c = 0; c < 4; c++) v4[c] = *(const float4*)&vs[j4 * 4 + c][d0];
#pragma unroll
        for (int r = 0; r < 2; r++) {
            po[r][0] = fmaf(s4[r].x, v4[0].x, po[r][0]);
            po[r][1] = fmaf(s4[r].x, v4[0].y, po[r][1]);
            po[r][2] = fmaf(s4[r].x, v4[0].z, po[r][2]);
            po[r][3] = fmaf(s4[r].x, v4[0].w, po[r][3]);
            po[r][0] = fmaf(s4[r].y, v4[1].x, po[r][0]);
            po[r][1] = fmaf(s4[r].y, v4[1].y, po[r][1]);
            po[r][2] = fmaf(s4[r].y, v4[1].z, po[r][2]);
            po[r][3] = fmaf(s4[r].y, v4[1].w, po[r][3]);
            po[r][0] = fmaf(s4[r].z, v4[2].x, po[r][0]);
            po[r][1] = fmaf(s4[r].z, v4[2].y, po[r][1]);
            po[r][2] = fmaf(s4[r].z, v4[2].z, po[r][2]);
            po[r][3] = fmaf(s4[r].z, v4[2].w, po[r][3]);
            po[r][0] = fmaf(s4[r].w, v4[3].x, po[r][0]);
            po[r][1] = fmaf(s4[r].w, v4[3].y, po[r][1]);
            po[r][2] = fmaf(s4[r].w, v4[3].z, po[r][2]);
            po[r][3] = fmaf(s4[r].w, v4[3].w, po[r][3]);
        }
    }
#pragma unroll
    for (int r = 0; r < 2; r++) {
        float4 o4 = make_float4(po[r][0], po[r][1], po[r][2], po[r][3]);
        *(float4*)(g_attnout + ((size_t)win * 64 + ip + r) * 256 + h * 32 + d0) = o4;
    }
}

// ---------------- block reduction helper ----------------
__device__ __forceinline__ float block_sum_256(float v, float* sh) {
    int t = threadIdx.x;
#pragma unroll
    for (int o = 16; o > 0; o >>= 1) v += __shfl_xor_sync(0xffffffffu, v, o);
    if ((t & 31) == 0) sh[t >> 5] = v;
    __syncthreads();
    if (t < 32) {
        float r = (t < 8) ? sh[t] : 0.f;
#pragma unroll
        for (int o = 4; o > 0; o >>= 1) r += __shfl_xor_sync(0xffffffffu, r, o);
        if (t == 0) sh[0] = r;
    }
    __syncthreads();
    float r = sh[0];
    __syncthreads();
    return r;
}

__global__ __launch_bounds__(256) void ln_res1_kernel(const float* __restrict__ x,
                                                      const float* __restrict__ g,
                                                      const float* __restrict__ b) {
    __shared__ float sh[8];
    int row = blockIdx.x;
    int t = threadIdx.x;
    int bb = row >> 12;
    int l = row & 4095;
    int r = l >> 6, c = l & 63;
    int rs = (r + 64 - SHIFT_) & 63, cs = (c + 64 - SHIFT_) & 63;
    int win = bb * 64 + (rs >> 3) * 8 + (cs >> 3);
    int n = (rs & 7) * 8 + (cs & 7);
    float y = g_tmp[((size_t)win * 64 + n) * 256 + t];
    float m = block_sum_256(y, sh) * (1.f / 256.f);
    float d = y - m;
    float v = block_sum_256(d * d, sh) * (1.f / 256.f);
    float o = d * rsqrtf(v + 1e-5f) * g[t] + b[t];
    g_xr[(size_t)row * 256 + t] = x[(size_t)row * 256 + t] + o;
}

__global__ __launch_bounds__(256) void ln_res2_kernel(float* __restrict__ out,
                                                      const float* __restrict__ g,
                                                      const float* __restrict__ b) {
    __shared__ float sh[8];
    int row = blockIdx.x;
    int t = threadIdx.x;
    float y = g_tmp[(size_t)row * 256 + t];
    float m = block_sum_256(y, sh) * (1.f / 256.f);
    float d = y - m;
    float v = block_sum_256(d * d, sh) * (1.f / 256.f);
    float o = d * rsqrtf(v + 1e-5f) * g[t] + b[t];
    out[(size_t)row * 256 + t] = g_xr[(size_t)row * 256 + t] + o;
}

// ---------------- launch ----------------
extern "C" void kernel_launch(void* const* d_in, const int* in_sizes, int n_in,
                              void* d_out, int out_size) {
    const float* x        = (const float*)d_in[0];
    const float* norm1_g  = (const float*)d_in[1];
    const float* norm1_b  = (const float*)d_in[2];
    const float* qkv_w    = (const float*)d_in[3];
    const float* q_bias   = (const float*)d_in[4];
    const float* v_bias   = (const float*)d_in[5];
    const float* logit_sc = (const float*)d_in[6];
    const float* cpb_w1   = (const float*)d_in[7];
    const float* cpb_b1   = (const float*)d_in[8];
    const float* cpb_w2   = (const float*)d_in[9];
    const float* proj_w   = (const float*)d_in[10];
    const float* proj_b   = (const float*)d_in[11];
    const float* norm2_g  = (const float*)d_in[12];
    const float* norm2_b  = (const float*)d_in[13];
    const float* fc1_w    = (const float*)d_in[14];
    const float* fc1_b    = (const float*)d_in[15];
    const float* fc2_w    = (const float*)d_in[16];
    const float* fc2_b    = (const float*)d_in[17];
    float* out = (float*)d_out;

    float *p_qkv, *p_attnout, *p_tmp, *p_xr, *p_hdn, *p_qkvb;
    cudaGetSymbolAddress((void**)&p_qkv, g_qkv);
    cudaGetSymbolAddress((void**)&p_attnout, g_attnout);
    cudaGetSymbolAddress((void**)&p_tmp, g_tmp);
    cudaGetSymbolAddress((void**)&p_xr, g_xr);
    cudaGetSymbolAddress((void**)&p_hdn, g_hdn);
    cudaGetSymbolAddress((void**)&p_qkvb, g_qkvb);

    fill_qkvb_kernel<<<1, 768>>>(q_bias, v_bias);
    cpb_kernel<<<1, 256>>>(cpb_w1, cpb_b1, cpb_w2);
    bias16_kernel<<<(HEADS * NTOK * NTOK) / 256, 256>>>();

    // QKV GEMM with fused shift+window gather on A
    mma_gemm_kernel<<<dim3(768 / TBN, M_ROWS / TBM), 256>>>(x, qkv_w, p_qkvb, p_qkv, 768, 256, 0, 1);

    attn_kernel<<<(M_ROWS / NTOK) * HEADS, 256>>>(logit_sc);

    mma_gemm_kernel<<<dim3(256 / TBN, M_ROWS / TBM), 256>>>(p_attnout, proj_w, proj_b, p_tmp, 256, 256, 0, 0);

    ln_res1_kernel<<<M_ROWS, 256>>>(x, norm1_g, norm1_b);

    mma_gemm_kernel<<<dim3(1024 / TBN, M_ROWS / TBM), 256>>>(p_xr, fc1_w, fc1_b, p_hdn, 1024, 256, 1, 0);
    mma_gemm_kernel<<<dim3(256 / TBN, M_ROWS / TBM), 256>>>(p_hdn, fc2_w, fc2_b, p_tmp, 256, 1024, 0, 0);

    ln_res2_kernel<<<M_ROWS, 256>>>(out, norm2_g, norm2_b);
}

// round 5
// speedup vs baseline: 2.5828x; 1.0610x over previous
#include <cuda_runtime.h>
#include <math.h>
#include <stdint.h>

#define DIMC 256
#define HEADS 8
#define NTOK 64
#define BATCH 32
#define LTOK 4096
#define M_ROWS (BATCH*LTOK)  // 131072
#define SHIFT_ 4

// ---------------- scratch ----------------
static __device__ float g_xw[(size_t)M_ROWS * DIMC];          // tf32-rounded windowed x
static __device__ float g_qkv[(size_t)M_ROWS * 3 * DIMC];
static __device__ float g_attnout[(size_t)M_ROWS * DIMC];     // tf32-rounded
static __device__ float g_tmp[(size_t)M_ROWS * DIMC];
static __device__ float g_xr[(size_t)M_ROWS * DIMC];          // full fp32 (residual)
static __device__ float g_xrt[(size_t)M_ROWS * DIMC];         // tf32-rounded (fc1 A)
static __device__ float g_hdn[(size_t)M_ROWS * 4 * DIMC];     // tf32-rounded
static __device__ float g_wt[786432];                         // rounded weights
static __device__ float g_cpb[225 * HEADS];
static __device__ float g_bias16[HEADS * NTOK * NTOK];
static __device__ float g_qkvb[3 * DIMC];

#define WT_QKV 0
#define WT_PROJ 196608
#define WT_FC1 262144
#define WT_FC2 524288

__device__ __forceinline__ uint32_t tf32u(float x) {
    uint32_t o;
    asm("cvt.rna.tf32.f32 %0, %1;" : "=r"(o) : "f"(x));
    return o;
}
__device__ __forceinline__ float tf32r(float x) { return __uint_as_float(tf32u(x)); }

// ---------------- tiny setup kernels ----------------
__global__ void fill_qkvb_kernel(const float* __restrict__ q_bias,
                                 const float* __restrict__ v_bias) {
    int t = threadIdx.x;
    float v;
    if (t < 256)      v = q_bias[t];
    else if (t < 512) v = 0.f;
    else              v = v_bias[t - 512];
    g_qkvb[t] = v;
}

__global__ void cpb_kernel(const float* __restrict__ w1, const float* __restrict__ b1,
                           const float* __restrict__ w2) {
    int i = threadIdx.x;
    if (i >= 225) return;
    float a  = (float)(i / 15) - 7.f;
    float bb = (float)(i % 15) - 7.f;
    float f0 = a  * (8.f / 7.f);
    float f1 = bb * (8.f / 7.f);
    f0 = copysignf(log2f(fabsf(f0) + 1.f) * (1.f / 3.f), f0);
    f1 = copysignf(log2f(fabsf(f1) + 1.f) * (1.f / 3.f), f1);
    float acc[HEADS];
#pragma unroll
    for (int h = 0; h < HEADS; h++) acc[h] = 0.f;
    for (int u = 0; u < 512; u++) {
        float hu = fmaf(w1[2 * u], f0, fmaf(w1[2 * u + 1], f1, b1[u]));
        hu = fmaxf(hu, 0.f);
#pragma unroll
        for (int h = 0; h < HEADS; h++) acc[h] = fmaf(hu, w2[h * 512 + u], acc[h]);
    }
#pragma unroll
    for (int h = 0; h < HEADS; h++) g_cpb[i * HEADS + h] = acc[h];
}

__global__ void bias16_kernel() {
    int gid = blockIdx.x * blockDim.x + threadIdx.x;
    if (gid >= HEADS * NTOK * NTOK) return;
    int h = gid >> 12;
    int ij = gid & 4095;
    int i = ij >> 6, j = ij & 63;
    int dr = (i >> 3) - (j >> 3);
    int dc = (i & 7) - (j & 7);
    int idx = (dr + 7) * 15 + (dc + 7);
    float x = g_cpb[idx * HEADS + h];
    g_bias16[gid] = 16.f / (1.f + expf(-x));
}

// round weights into g_wt
__global__ void round_w_kernel(const float* __restrict__ qkv_w, const float* __restrict__ proj_w,
                               const float* __restrict__ fc1_w, const float* __restrict__ fc2_w) {
    int i4 = blockIdx.x * blockDim.x + threadIdx.x;   // over 786432/4 float4
    if (i4 >= 196608) return;
    const float* src;
    int off = i4 * 4;
    if (off < WT_PROJ)           { src = qkv_w  + off; }
    else if (off < WT_FC1)       { src = proj_w + (off - WT_PROJ); }
    else if (off < WT_FC2)       { src = fc1_w  + (off - WT_FC1); }
    else                         { src = fc2_w  + (off - WT_FC2); }
    float4 v = *(const float4*)src;
    v.x = tf32r(v.x); v.y = tf32r(v.y); v.z = tf32r(v.z); v.w = tf32r(v.w);
    *(float4*)(g_wt + off) = v;
}

// shift+window gather with tf32 rounding
__global__ void gather_round_kernel(const float* __restrict__ x) {
    int t = blockIdx.x * blockDim.x + threadIdx.x;  // M_ROWS*64 float4
    int m = t >> 6, c4 = t & 63;
    int win = m >> 6, n = m & 63;
    int b = win >> 6, wr = (win >> 3) & 7, wc = win & 7;
    int r = (wr * 8 + (n >> 3) + SHIFT_) & 63;
    int c = (wc * 8 + (n & 7) + SHIFT_) & 63;
    float4 v = ((const float4*)(x + ((size_t)b * LTOK + r * 64 + c) * DIMC))[c4];
    v.x = tf32r(v.x); v.y = tf32r(v.y); v.z = tf32r(v.z); v.w = tf32r(v.w);
    ((float4*)(g_xw + (size_t)m * DIMC))[c4] = v;
}

// ---------------- tf32 GEMM, 3-stage cp.async, no in-loop cvt ----------------
// C[M,N] = A[M,K] @ W[N,K]^T + bias. Tile 128x128xBK16, 8 warps 64x32.
#define TBK 16
#define ROWF 20
#define SLOTF 5120          // floats per stage (A 2560 + W 2560)
#define SLOTB 20480         // bytes per stage
#define STAGES 3

#define CP16(sm, gp) asm volatile("cp.async.cg.shared.global [%0], [%1], 16;" :: "r"(sm), "l"(gp))
#define CPCOMMIT() asm volatile("cp.async.commit_group;" ::: "memory")
#define CPWAIT1() asm volatile("cp.async.wait_group 1;" ::: "memory")

__global__ __launch_bounds__(256, 2) void mma_gemm_kernel(
    const float* __restrict__ A, const float* __restrict__ W,
    const float* __restrict__ bias, float* __restrict__ C,
    int N, int K, int gelu) {
    extern __shared__ float sm[];
    int tid = threadIdx.x;
    int wid = tid >> 5, lane = tid & 31;
    int wm = wid >> 2, wn = wid & 3;
    int brow = blockIdx.y * 128, bcol = blockIdx.x * 128;
    int lq = lane >> 2, lr = lane & 3;

    int r0 = tid >> 2, c0 = (tid & 3) * 4;
    const float* aptr0 = A + (size_t)(brow + r0) * K + c0;
    const float* aptr1 = A + (size_t)(brow + r0 + 64) * K + c0;
    const float* wptr0 = W + (size_t)(bcol + r0) * K + c0;
    const float* wptr1 = W + (size_t)(bcol + r0 + 64) * K + c0;

    uint32_t sbase = (uint32_t)__cvta_generic_to_shared(sm);
    uint32_t aoff = sbase + (r0 * ROWF + c0) * 4;
    uint32_t woff = aoff + 2560 * 4;
    const uint32_t rowoff = 64 * ROWF * 4;

    float acc[4][4][4];
#pragma unroll
    for (int mi = 0; mi < 4; mi++)
#pragma unroll
        for (int ni = 0; ni < 4; ni++)
#pragma unroll
            for (int r = 0; r < 4; r++) acc[mi][ni][r] = 0.f;

    int KT = K / TBK;
    // prologue: prefetch tiles 0,1
#pragma unroll
    for (int p = 0; p < 2; p++) {
        uint32_t bo = p * SLOTB;
        int k0 = p * TBK;
        CP16(aoff + bo, aptr0 + k0); CP16(aoff + bo + rowoff, aptr1 + k0);
        CP16(woff + bo, wptr0 + k0); CP16(woff + bo + rowoff, wptr1 + k0);
        CPCOMMIT();
    }

    for (int kt = 0; kt < KT; kt++) {
        CPWAIT1();
        __syncthreads();
        if (kt + 2 < KT) {
            int slot = (kt + 2) % STAGES;
            uint32_t bo = slot * (uint32_t)SLOTB;
            int k0 = (kt + 2) * TBK;
            CP16(aoff + bo, aptr0 + k0); CP16(aoff + bo + rowoff, aptr1 + k0);
            CP16(woff + bo, wptr0 + k0); CP16(woff + bo + rowoff, wptr1 + k0);
        }
        CPCOMMIT();   // empty group when nothing prefetched keeps wait_group 1 sound

        const float* sa = sm + (kt % STAGES) * SLOTF;
        const float* sw = sa + 2560;
#pragma unroll
        for (int kk = 0; kk < TBK; kk += 8) {
            uint32_t af[4][4];
#pragma unroll
            for (int mi = 0; mi < 4; mi++) {
                int rb = wm * 64 + mi * 16 + lq;
                af[mi][0] = __float_as_uint(sa[rb * ROWF + kk + lr]);
                af[mi][1] = __float_as_uint(sa[(rb + 8) * ROWF + kk + lr]);
                af[mi][2] = __float_as_uint(sa[rb * ROWF + kk + 4 + lr]);
                af[mi][3] = __float_as_uint(sa[(rb + 8) * ROWF + kk + 4 + lr]);
            }
            uint32_t bf[4][2];
#pragma unroll
            for (int ni = 0; ni < 4; ni++) {
                int nb = wn * 32 + ni * 8 + lq;
                bf[ni][0] = __float_as_uint(sw[nb * ROWF + kk + lr]);
                bf[ni][1] = __float_as_uint(sw[nb * ROWF + kk + 4 + lr]);
            }
#pragma unroll
            for (int mi = 0; mi < 4; mi++)
#pragma unroll
                for (int ni = 0; ni < 4; ni++) {
                    asm volatile(
                        "mma.sync.aligned.m16n8k8.row.col.f32.tf32.tf32.f32 "
                        "{%0,%1,%2,%3}, {%4,%5,%6,%7}, {%8,%9}, {%0,%1,%2,%3};"
                        : "+f"(acc[mi][ni][0]), "+f"(acc[mi][ni][1]),
                          "+f"(acc[mi][ni][2]), "+f"(acc[mi][ni][3])
                        : "r"(af[mi][0]), "r"(af[mi][1]), "r"(af[mi][2]), "r"(af[mi][3]),
                          "r"(bf[ni][0]), "r"(bf[ni][1]));
                }
        }
    }

#pragma unroll
    for (int mi = 0; mi < 4; mi++) {
#pragma unroll
        for (int ni = 0; ni < 4; ni++) {
            int col = bcol + wn * 32 + ni * 8 + lr * 2;
            float b0 = bias[col], b1 = bias[col + 1];
            int rr = brow + wm * 64 + mi * 16 + lq;
            float v0 = acc[mi][ni][0] + b0;
            float v1 = acc[mi][ni][1] + b1;
            float v2 = acc[mi][ni][2] + b0;
            float v3 = acc[mi][ni][3] + b1;
            if (gelu) {
                v0 = 0.5f * v0 * (1.f + erff(v0 * 0.70710678118654752f));
                v1 = 0.5f * v1 * (1.f + erff(v1 * 0.70710678118654752f));
                v2 = 0.5f * v2 * (1.f + erff(v2 * 0.70710678118654752f));
                v3 = 0.5f * v3 * (1.f + erff(v3 * 0.70710678118654752f));
                v0 = tf32r(v0); v1 = tf32r(v1); v2 = tf32r(v2); v3 = tf32r(v3);
            }
            *(float2*)(C + (size_t)rr * N + col) = make_float2(v0, v1);
            *(float2*)(C + (size_t)(rr + 8) * N + col) = make_float2(v2, v3);
        }
    }
}

// ---------------- fused window attention, register-blocked ----------------
__global__ __launch_bounds__(256) void attn_kernel(const float* __restrict__ logit_scale) {
    __shared__ float qs[64][36];
    __shared__ float ksT[32][68];
    __shared__ float vs[64][36];
    __shared__ float Ss[64][68];
    __shared__ int lab[64];

    int blk = blockIdx.x;
    int win = blk >> 3, h = blk & 7;
    int t = threadIdx.x;

    size_t base = (size_t)win * 64 * 768;
#pragma unroll
    for (int f = t; f < 512; f += 256) {
        int n = f >> 3, d4 = (f & 7) * 4;
        const float* rowp = g_qkv + base + (size_t)n * 768 + h * 32 + d4;
        float4 q4 = *(const float4*)(rowp);
        float4 k4 = *(const float4*)(rowp + 256);
        float4 v4 = *(const float4*)(rowp + 512);
        *(float4*)&qs[n][d4] = q4;
        ksT[d4 + 0][n] = k4.x; ksT[d4 + 1][n] = k4.y;
        ksT[d4 + 2][n] = k4.z; ksT[d4 + 3][n] = k4.w;
        *(float4*)&vs[n][d4] = v4;
    }
    if (t < 64) {
        int wr = (win >> 3) & 7, wc = win & 7;
        int rs = wr * 8 + (t >> 3), cs = wc * 8 + (t & 7);
        int lr2 = rs < 56 ? 0 : (rs < 60 ? 1 : 2);
        int lc2 = cs < 56 ? 0 : (cs < 60 ? 1 : 2);
        lab[t] = lr2 * 3 + lc2;
    }
    __syncthreads();

    {
        int row = t >> 2, j0 = (t & 3) * 8;
        float sq = 0.f;
#pragma unroll
        for (int j = 0; j < 8; j++) { float a = qs[row][j0 + j]; sq = fmaf(a, a, sq); }
        sq += __shfl_xor_sync(0xffffffffu, sq, 1);
        sq += __shfl_xor_sync(0xffffffffu, sq, 2);
        float iq = 1.f / fmaxf(sqrtf(sq), 1e-12f);
#pragma unroll
        for (int j = 0; j < 8; j++) qs[row][j0 + j] *= iq;
    }
    {
        int tok = t >> 2, d0 = (t & 3) * 8;
        float sk = 0.f;
#pragma unroll
        for (int j = 0; j < 8; j++) { float b = ksT[d0 + j][tok]; sk = fmaf(b, b, sk); }
        sk += __shfl_xor_sync(0xffffffffu, sk, 1);
        sk += __shfl_xor_sync(0xffffffffu, sk, 2);
        float ik = 1.f / fmaxf(sqrtf(sk), 1e-12f);
#pragma unroll
        for (int j = 0; j < 8; j++) ksT[d0 + j][tok] *= ik;
    }
    __syncthreads();

    float scale = expf(fminf(logit_scale[h], 4.6051701859880914f));

    int ti = t >> 4, tj = t & 15;
    int i0 = ti * 4, j0 = tj * 4;
    float sv[4][4];
#pragma unroll
    for (int r = 0; r < 4; r++)
#pragma unroll
        for (int c = 0; c < 4; c++) sv[r][c] = 0.f;

#pragma unroll
    for (int kk = 0; kk < 32; kk++) {
        float4 kq = *(const float4*)&ksT[kk][j0];
        float qr[4];
#pragma unroll
        for (int r = 0; r < 4; r++) qr[r] = qs[i0 + r][kk];
#pragma unroll
        for (int r = 0; r < 4; r++) {
            sv[r][0] = fmaf(qr[r], kq.x, sv[r][0]);
            sv[r][1] = fmaf(qr[r], kq.y, sv[r][1]);
            sv[r][2] = fmaf(qr[r], kq.z, sv[r][2]);
            sv[r][3] = fmaf(qr[r], kq.w, sv[r][3]);
        }
    }

    int li[4], lj[4];
#pragma unroll
    for (int r = 0; r < 4; r++) li[r] = lab[i0 + r];
#pragma unroll
    for (int c = 0; c < 4; c++) lj[c] = lab[j0 + c];
    const float* btab = g_bias16 + (size_t)h * 4096;

#pragma unroll
    for (int r = 0; r < 4; r++) {
        float4 b4 = *(const float4*)(btab + (i0 + r) * 64 + j0);
        sv[r][0] = fmaf(sv[r][0], scale, b4.x) + ((lj[0] != li[r]) ? -100.f : 0.f);
        sv[r][1] = fmaf(sv[r][1], scale, b4.y) + ((lj[1] != li[r]) ? -100.f : 0.f);
        sv[r][2] = fmaf(sv[r][2], scale, b4.z) + ((lj[2] != li[r]) ? -100.f : 0.f);
        sv[r][3] = fmaf(sv[r][3], scale, b4.w) + ((lj[3] != li[r]) ? -100.f : 0.f);
        float m = fmaxf(fmaxf(sv[r][0], sv[r][1]), fmaxf(sv[r][2], sv[r][3]));
#pragma unroll
        for (int o = 1; o < 16; o <<= 1) m = fmaxf(m, __shfl_xor_sync(0xffffffffu, m, o));
        float s = 0.f;
#pragma unroll
        for (int c = 0; c < 4; c++) { sv[r][c] = expf(sv[r][c] - m); s += sv[r][c]; }
#pragma unroll
        for (int o = 1; o < 16; o <<= 1) s += __shfl_xor_sync(0xffffffffu, s, o);
        float inv = 1.f / s;
        float4 p = make_float4(sv[r][0] * inv, sv[r][1] * inv, sv[r][2] * inv, sv[r][3] * inv);
        *(float4*)&Ss[i0 + r][j0] = p;
    }
    __syncthreads();

    int tr = t >> 3, td = t & 7;
    int ip = tr * 2, d0 = td * 4;
    float po[2][4];
#pragma unroll
    for (int r = 0; r < 2; r++)
#pragma unroll
        for (int c = 0; c < 4; c++) po[r][c] = 0.f;

#pragma unroll
    for (int j4 = 0; j4 < 16; j4++) {
        float4 s4[2];
#pragma unroll
        for (int r = 0; r < 2; r++) s4[r] = *(const float4*)&Ss[ip + r][j4 * 4];
        float4 v4[4];
#pragma unroll
        for (int c = 0; c < 4; c++) v4[c] = *(const float4*)&vs[j4 * 4 + c][d0];
#pragma unroll
        for (int r = 0; r < 2; r++) {
            po[r][0] = fmaf(s4[r].x, v4[0].x, po[r][0]);
            po[r][1] = fmaf(s4[r].x, v4[0].y, po[r][1]);
            po[r][2] = fmaf(s4[r].x, v4[0].z, po[r][2]);
            po[r][3] = fmaf(s4[r].x, v4[0].w, po[r][3]);
            po[r][0] = fmaf(s4[r].y, v4[1].x, po[r][0]);
            po[r][1] = fmaf(s4[r].y, v4[1].y, po[r][1]);
            po[r][2] = fmaf(s4[r].y, v4[1].z, po[r][2]);
            po[r][3] = fmaf(s4[r].y, v4[1].w, po[r][3]);
            po[r][0] = fmaf(s4[r].z, v4[2].x, po[r][0]);
            po[r][1] = fmaf(s4[r].z, v4[2].y, po[r][1]);
            po[r][2] = fmaf(s4[r].z, v4[2].z, po[r][2]);
            po[r][3] = fmaf(s4[r].z, v4[2].w, po[r][3]);
            po[r][0] = fmaf(s4[r].w, v4[3].x, po[r][0]);
            po[r][1] = fmaf(s4[r].w, v4[3].y, po[r][1]);
            po[r][2] = fmaf(s4[r].w, v4[3].z, po[r][2]);
            po[r][3] = fmaf(s4[r].w, v4[3].w, po[r][3]);
        }
    }
#pragma unroll
    for (int r = 0; r < 2; r++) {
        float4 o4 = make_float4(tf32r(po[r][0]), tf32r(po[r][1]),
                                tf32r(po[r][2]), tf32r(po[r][3]));
        *(float4*)(g_attnout + ((size_t)win * 64 + ip + r) * 256 + h * 32 + d0) = o4;
    }
}

// ---------------- block reduction helper ----------------
__device__ __forceinline__ float block_sum_256(float v, float* sh) {
    int t = threadIdx.x;
#pragma unroll
    for (int o = 16; o > 0; o >>= 1) v += __shfl_xor_sync(0xffffffffu, v, o);
    if ((t & 31) == 0) sh[t >> 5] = v;
    __syncthreads();
    if (t < 32) {
        float r = (t < 8) ? sh[t] : 0.f;
#pragma unroll
        for (int o = 4; o > 0; o >>= 1) r += __shfl_xor_sync(0xffffffffu, r, o);
        if (t == 0) sh[0] = r;
    }
    __syncthreads();
    float r = sh[0];
    __syncthreads();
    return r;
}

__global__ __launch_bounds__(256) void ln_res1_kernel(const float* __restrict__ x,
                                                      const float* __restrict__ g,
                                                      const float* __restrict__ b) {
    __shared__ float sh[8];
    int row = blockIdx.x;
    int t = threadIdx.x;
    int bb = row >> 12;
    int l = row & 4095;
    int r = l >> 6, c = l & 63;
    int rs = (r + 64 - SHIFT_) & 63, cs = (c + 64 - SHIFT_) & 63;
    int win = bb * 64 + (rs >> 3) * 8 + (cs >> 3);
    int n = (rs & 7) * 8 + (cs & 7);
    float y = g_tmp[((size_t)win * 64 + n) * 256 + t];
    float m = block_sum_256(y, sh) * (1.f / 256.f);
    float d = y - m;
    float v = block_sum_256(d * d, sh) * (1.f / 256.f);
    float o = d * rsqrtf(v + 1e-5f) * g[t] + b[t];
    float xr = x[(size_t)row * 256 + t] + o;
    g_xr[(size_t)row * 256 + t] = xr;
    g_xrt[(size_t)row * 256 + t] = tf32r(xr);
}

__global__ __launch_bounds__(256) void ln_res2_kernel(float* __restrict__ out,
                                                      const float* __restrict__ g,
                                                      const float* __restrict__ b) {
    __shared__ float sh[8];
    int row = blockIdx.x;
    int t = threadIdx.x;
    float y = g_tmp[(size_t)row * 256 + t];
    float m = block_sum_256(y, sh) * (1.f / 256.f);
    float d = y - m;
    float v = block_sum_256(d * d, sh) * (1.f / 256.f);
    float o = d * rsqrtf(v + 1e-5f) * g[t] + b[t];
    out[(size_t)row * 256 + t] = g_xr[(size_t)row * 256 + t] + o;
}

// ---------------- launch ----------------
extern "C" void kernel_launch(void* const* d_in, const int* in_sizes, int n_in,
                              void* d_out, int out_size) {
    const float* x        = (const float*)d_in[0];
    const float* norm1_g  = (const float*)d_in[1];
    const float* norm1_b  = (const float*)d_in[2];
    const float* qkv_w    = (const float*)d_in[3];
    const float* q_bias   = (const float*)d_in[4];
    const float* v_bias   = (const float*)d_in[5];
    const float* logit_sc = (const float*)d_in[6];
    const float* cpb_w1   = (const float*)d_in[7];
    const float* cpb_b1   = (const float*)d_in[8];
    const float* cpb_w2   = (const float*)d_in[9];
    const float* proj_w   = (const float*)d_in[10];
    const float* proj_b   = (const float*)d_in[11];
    const float* norm2_g  = (const float*)d_in[12];
    const float* norm2_b  = (const float*)d_in[13];
    const float* fc1_w    = (const float*)d_in[14];
    const float* fc1_b    = (const float*)d_in[15];
    const float* fc2_w    = (const float*)d_in[16];
    const float* fc2_b    = (const float*)d_in[17];
    float* out = (float*)d_out;

    float *p_xw, *p_qkv, *p_attnout, *p_tmp, *p_xrt, *p_hdn, *p_qkvb, *p_wt;
    cudaGetSymbolAddress((void**)&p_xw, g_xw);
    cudaGetSymbolAddress((void**)&p_qkv, g_qkv);
    cudaGetSymbolAddress((void**)&p_attnout, g_attnout);
    cudaGetSymbolAddress((void**)&p_tmp, g_tmp);
    cudaGetSymbolAddress((void**)&p_xrt, g_xrt);
    cudaGetSymbolAddress((void**)&p_hdn, g_hdn);
    cudaGetSymbolAddress((void**)&p_qkvb, g_qkvb);
    cudaGetSymbolAddress((void**)&p_wt, g_wt);

    static int smem_set = 0;
    if (!smem_set) {
        cudaFuncSetAttribute(mma_gemm_kernel,
                             cudaFuncAttributeMaxDynamicSharedMemorySize, STAGES * SLOTB);
        smem_set = 1;
    }

    fill_qkvb_kernel<<<1, 768>>>(q_bias, v_bias);
    cpb_kernel<<<1, 256>>>(cpb_w1, cpb_b1, cpb_w2);
    bias16_kernel<<<(HEADS * NTOK * NTOK) / 256, 256>>>();
    round_w_kernel<<<768, 256>>>(qkv_w, proj_w, fc1_w, fc2_w);
    gather_round_kernel<<<(M_ROWS * 64) / 256, 256>>>(x);

    mma_gemm_kernel<<<dim3(6, 1024), 256, STAGES * SLOTB>>>(p_xw, p_wt + WT_QKV, p_qkvb, p_qkv, 768, 256, 0);

    attn_kernel<<<(M_ROWS / NTOK) * HEADS, 256>>>(logit_sc);

    mma_gemm_kernel<<<dim3(2, 1024), 256, STAGES * SLOTB>>>(p_attnout, p_wt + WT_PROJ, proj_b, p_tmp, 256, 256, 0);

    ln_res1_kernel<<<M_ROWS, 256>>>(x, norm1_g, norm1_b);

    mma_gemm_kernel<<<dim3(8, 1024), 256, STAGES * SLOTB>>>(p_xrt, p_wt + WT_FC1, fc1_b, p_hdn, 1024, 256, 1);
    mma_gemm_kernel<<<dim3(2, 1024), 256, STAGES * SLOTB>>>(p_hdn, p_wt + WT_FC2, fc2_b, p_tmp, 256, 1024, 0);

    ln_res2_kernel<<<M_ROWS, 256>>>(out, norm2_g, norm2_b);
}